// round 6
// baseline (speedup 1.0000x reference)
#include <cuda_runtime.h>
#include <cuda_fp16.h>
#include <cstdint>

// ---------------------------------------------------------------------------
// LSTM cell w/ diagonal peepholes, 2 launches:
//   1) convert: x|hx -> g_A fp16 [4096x2048], W_ih|W_hh -> g_W fp16 [4096x2048]
//   2) fused GEMM+epilogue: per CTA computes a 128(batch) x 128(N) tile where
//      the 128 N-columns are 4 gate strips of 32 h-values, then applies the
//      LSTM elementwise math in-CTA and writes hy/cy directly.
// tcgen05 unavailable (harness PTX targets plain sm_103, no 'a' features).
// ---------------------------------------------------------------------------

#define MB 4096
#define HD 1024
#define KT 2048

#define BM 128
#define BN 128
#define BKH 64              // K-halves per stage
#define RSB 144             // smem row stride bytes (128B data + 16 pad)
#define TILE_BYTES (BM * RSB)          // 18432
#define STG_BYTES  (2 * TILE_BYTES)    // 36864 (A then B)
#define SMEM_BYTES (3 * STG_BYTES)     // 110592 (3 stages)

// epilogue smem overlay — BYTE offsets (reuses pipeline buffers after mainloop)
#define EPS          132                        // fp32 acc row stride in floats
#define EPB_GACC     0                          // 128 * 132 * 4 = 67584 bytes
#define EPB_BS       (128 * EPS * 4)            // 67584: 128 floats (bias sums)
#define EPB_PI       (EPB_BS + 512)             // 68096: 32 floats
#define EPB_PF       (EPB_PI + 128)             // 68224: 32 floats (end 68352)

__device__ __half g_A[(size_t)MB * KT];
__device__ __half g_W[(size_t)4096 * KT];

// ----------------------------- helpers ------------------------------------
__device__ __forceinline__ uint32_t smem_u32(const void* p) {
    uint32_t a;
    asm("{ .reg .u64 t; cvta.to.shared.u64 t, %1; cvt.u32.u64 %0, t; }"
        : "=r"(a) : "l"(p));
    return a;
}
__device__ __forceinline__ void cp16(uint32_t dst, const void* src) {
    asm volatile("cp.async.cg.shared.global [%0], [%1], 16;"
                 :: "r"(dst), "l"(src) : "memory");
}
#define CP_COMMIT() asm volatile("cp.async.commit_group;" ::: "memory")
#define CP_WAIT1()  asm volatile("cp.async.wait_group 1;"  ::: "memory")

#define LDSM_X4(r0, r1, r2, r3, addr) \
    asm volatile("ldmatrix.sync.aligned.m8n8.x4.shared.b16 {%0,%1,%2,%3}, [%4];" \
                 : "=r"(r0), "=r"(r1), "=r"(r2), "=r"(r3) : "r"(addr))

#define MMA16816(c, a, b) \
    asm volatile("mma.sync.aligned.m16n8k16.row.col.f32.f16.f16.f32 " \
                 "{%0,%1,%2,%3}, {%4,%5,%6,%7}, {%8,%9}, {%0,%1,%2,%3};" \
                 : "+f"((c)[0]), "+f"((c)[1]), "+f"((c)[2]), "+f"((c)[3]) \
                 : "r"((a)[0]), "r"((a)[1]), "r"((a)[2]), "r"((a)[3]), \
                   "r"((b)[0]), "r"((b)[1]))

__device__ __forceinline__ float sigmoidf_(float v) {
    return 1.0f / (1.0f + expf(-v));
}

// ----------------------------- convert ------------------------------------
// Each thread converts 16 consecutive fp32 (4 float4, MLP=4) to fp16.
__global__ __launch_bounds__(256)
void convert_f16(const float* __restrict__ x,  const float* __restrict__ hx,
                 const float* __restrict__ wih, const float* __restrict__ whh) {
    const size_t NA16 = (size_t)MB * KT / 16;   // 512K picks for A, 512K for W
    const size_t id = (size_t)blockIdx.x * blockDim.x + threadIdx.x;
    const size_t j   = (id < NA16) ? id : id - NA16;
    const size_t row = j >> 7;                  // 128 16-elem picks per row
    const size_t k16 = (j & 127) * 16;
    const float* src;
    __half* dst;
    if (id < NA16) {
        src = (k16 < HD) ? (x + row * HD + k16) : (hx + row * HD + (k16 - HD));
        dst = g_A + j * 16;
    } else {
        src = (k16 < HD) ? (wih + row * HD + k16) : (whh + row * HD + (k16 - HD));
        dst = g_W + j * 16;
    }
    float4 v0 = *(const float4*)(src);
    float4 v1 = *(const float4*)(src + 4);
    float4 v2 = *(const float4*)(src + 8);
    float4 v3 = *(const float4*)(src + 12);
    __half2 h_[8];
    h_[0] = __floats2half2_rn(v0.x, v0.y); h_[1] = __floats2half2_rn(v0.z, v0.w);
    h_[2] = __floats2half2_rn(v1.x, v1.y); h_[3] = __floats2half2_rn(v1.z, v1.w);
    h_[4] = __floats2half2_rn(v2.x, v2.y); h_[5] = __floats2half2_rn(v2.z, v2.w);
    h_[6] = __floats2half2_rn(v3.x, v3.y); h_[7] = __floats2half2_rn(v3.z, v3.w);
    *(uint4*)(dst)     = *(uint4*)&h_[0];
    *(uint4*)(dst + 8) = *(uint4*)&h_[4];
}

// ------------------------ fused GEMM + LSTM epilogue -----------------------
__global__ __launch_bounds__(256, 2)
void lstm_gemm_fused(const float* __restrict__ cx,
                     const float* __restrict__ b_ih,
                     const float* __restrict__ b_hh,
                     const float* __restrict__ wpi,
                     const float* __restrict__ wpf,
                     float* __restrict__ out) {
    extern __shared__ char smem[];
    const uint32_t sb = smem_u32(smem);

    const int tid  = threadIdx.x;
    const int lane = tid & 31;
    const int warp = tid >> 5;
    const int wm   = warp >> 2;          // 0..1 (64 rows each)
    const int wn   = warp & 3;           // 0..3 (32 cols each = one gate)
    const int bm   = blockIdx.y * BM;    // batch block
    const int h0   = blockIdx.x * 32;    // 32 h-values per CTA

    // global source pointers for this thread's 4 fill chunks (advance by BKH)
    const __half* pa[4];
    const __half* pw[4];
    uint32_t so[4];
    #pragma unroll
    for (int i = 0; i < 4; i++) {
        const int f = tid + i * 256;
        const int r = f >> 3, c = f & 7;
        pa[i] = g_A + (size_t)(bm + r) * KT + c * 8;
        const int wr = ((r >> 5) << 10) + h0 + (r & 31);   // gate-strip row
        pw[i] = g_W + (size_t)wr * KT + c * 8;
        so[i] = (uint32_t)r * RSB + (uint32_t)c * 16;
    }

    const uint32_t aoff = (uint32_t)(lane & 15) * RSB + (uint32_t)(lane >> 4) * 16;
    const uint32_t boff = (uint32_t)(lane & 7) * RSB + (uint32_t)((lane >> 3) & 1) * 16
                        + (uint32_t)(lane >> 4) * (8 * RSB);

#define FILL(s_) do {                                                          \
        const uint32_t sa_ = sb + (uint32_t)(s_) * STG_BYTES;                  \
        _Pragma("unroll")                                                      \
        for (int i_ = 0; i_ < 4; i_++) {                                       \
            cp16(sa_ + so[i_], pa[i_]);                                        \
            cp16(sa_ + TILE_BYTES + so[i_], pw[i_]);                           \
            pa[i_] += BKH; pw[i_] += BKH;                                      \
        }                                                                      \
    } while (0)

    FILL(0); CP_COMMIT();
    FILL(1); CP_COMMIT();

    float acc[4][4][4];
    #pragma unroll
    for (int i = 0; i < 4; i++)
        #pragma unroll
        for (int j = 0; j < 4; j++)
            #pragma unroll
            for (int e = 0; e < 4; e++) acc[i][j][e] = 0.0f;

    #pragma unroll 1
    for (int kt = 0; kt < KT / BKH; kt++) {       // 32 iterations
        const int s = kt % 3;
        CP_WAIT1();
        __syncthreads();
        if (kt + 2 < KT / BKH) FILL((kt + 2) % 3);
        CP_COMMIT();

        const uint32_t sa = sb + (uint32_t)s * STG_BYTES;
        const uint32_t sw = sa + TILE_BYTES;
        #pragma unroll
        for (int ks = 0; ks < 4; ks++) {
            uint32_t a[4][4], b[4][2];
            #pragma unroll
            for (int mt = 0; mt < 4; mt++) {
                const uint32_t ad = sa + (uint32_t)(wm * 64 + mt * 16) * RSB
                                       + (uint32_t)ks * 32 + aoff;
                LDSM_X4(a[mt][0], a[mt][1], a[mt][2], a[mt][3], ad);
            }
            #pragma unroll
            for (int np = 0; np < 2; np++) {
                const uint32_t bd = sw + (uint32_t)(wn * 32 + np * 16) * RSB
                                       + (uint32_t)ks * 32 + boff;
                LDSM_X4(b[np * 2][0], b[np * 2][1],
                        b[np * 2 + 1][0], b[np * 2 + 1][1], bd);
            }
            #pragma unroll
            for (int mt = 0; mt < 4; mt++)
                #pragma unroll
                for (int nt = 0; nt < 4; nt++)
                    MMA16816(acc[mt][nt], a[mt], b[nt]);
        }
    }
#undef FILL

    // ------------------ epilogue: stage accs through smem ------------------
    __syncthreads();                       // all stage buffers consumed
    float* GA = (float*)(smem + EPB_GACC); // [128][EPS] fp32 accs
    float* BS = (float*)(smem + EPB_BS);   // 128 floats: b_ih+b_hh per gate col
    float* PI = (float*)(smem + EPB_PI);   // 32 floats: diag(W_peephole_i)
    float* PF = (float*)(smem + EPB_PF);   // 32 floats: diag(W_peephole_f)

    const int g2 = lane >> 2;
    const int tc = lane & 3;
    #pragma unroll
    for (int mt = 0; mt < 4; mt++) {
        #pragma unroll
        for (int nt = 0; nt < 4; nt++) {
            const int row = wm * 64 + mt * 16 + g2;
            const int col = wn * 32 + nt * 8 + tc * 2;
            *(float2*)(GA + (size_t)row * EPS + col) =
                make_float2(acc[mt][nt][0], acc[mt][nt][1]);
            *(float2*)(GA + (size_t)(row + 8) * EPS + col) =
                make_float2(acc[mt][nt][2], acc[mt][nt][3]);
        }
    }
    if (tid < 128) {
        const int gcol = ((tid >> 5) << 10) + h0 + (tid & 31);
        BS[tid] = b_ih[gcol] + b_hh[gcol];
    } else if (tid < 160) {
        const int j = tid - 128;
        PI[j] = wpi[(size_t)(h0 + j) * (HD + 1)];
        PF[j] = wpf[(size_t)(h0 + j) * (HD + 1)];
    }
    __syncthreads();

    // each thread: 16 (b,h) pairs; lane == j (h index), coalesced I/O
    #pragma unroll 4
    for (int q = 0; q < 16; q++) {
        const int p = q * 256 + tid;
        const int r = p >> 5;              // batch row within tile
        const int j = p & 31;              // h within 32
        const float* gr = GA + (size_t)r * EPS;
        const float ig = gr[j]      + BS[j];
        const float fg = gr[32 + j] + BS[32 + j];
        const float gg = gr[64 + j] + BS[64 + j];
        const float og = gr[96 + j] + BS[96 + j];
        const float c  = cx[(size_t)(bm + r) * HD + h0 + j];
        const float i_s = sigmoidf_(ig + c * PI[j]);
        const float f_s = sigmoidf_(fg + c * PF[j]);
        const float g_t = tanhf(gg);
        const float cy  = f_s * c + i_s * g_t;
        const float o_s = sigmoidf_(og + cy * PF[j]);   // ref reuses W_f
        const float hy  = o_s * tanhf(cy);
        out[(size_t)(bm + r) * HD + h0 + j] = hy;
        out[(size_t)MB * HD + (size_t)(bm + r) * HD + h0 + j] = cy;
    }
}

// ---------------------------------------------------------------------------
extern "C" void kernel_launch(void* const* d_in, const int* in_sizes, int n_in,
                              void* d_out, int out_size) {
    const float* x    = (const float*)d_in[0];
    const float* hx   = (const float*)d_in[1];
    const float* cx   = (const float*)d_in[2];
    const float* w_ih = (const float*)d_in[3];
    const float* w_hh = (const float*)d_in[4];
    const float* b_ih = (const float*)d_in[5];
    const float* b_hh = (const float*)d_in[6];
    const float* wpi  = (const float*)d_in[7];
    const float* wpf  = (const float*)d_in[8];
    // d_in[9] (W_peephole_o) unused: reference reuses W_peephole_f.
    float* out = (float*)d_out;

    // 1M threads: 512K x 16-elem picks for A, same for W
    convert_f16<<<4096, 256>>>(x, hx, w_ih, w_hh);

    static int smem_set = 0;
    if (!smem_set) {
        cudaFuncSetAttribute(lstm_gemm_fused,
                             cudaFuncAttributeMaxDynamicSharedMemorySize,
                             SMEM_BYTES);
        smem_set = 1;
    }
    dim3 grid(32, 32);   // 32 h-blocks x 32 batch-blocks
    lstm_gemm_fused<<<grid, 256, SMEM_BYTES>>>(cx, b_ih, b_hh, wpi, wpf, out);
}